// round 5
// baseline (speedup 1.0000x reference)
#include <cuda_runtime.h>
#include <cuda_fp16.h>

#define N_R 40000
#define N_U 30000
#define N_P 30000
#define NN  100000
#define EE  1600000
#define F   128
#define C   40
#define ZC  21            // stacked width: 5 + 7 + 6 + 3 bias-count cols
#define TN  128           // nodes per MLP block
#define HP  130           // padded h row stride (floats)
#define FP2 130           // padded W2 pair-row stride (float2 units)
#define C2  20            // half2 output columns

// ---------------- device scratch (static, no allocation) ----------------
__device__ float   g_z [(size_t)(NN + 128) * ZC];
__device__ __half2 g_h2h[(size_t)NN * C2 + 64];
__device__ float   g_Ws[ZC * F];
__device__ int     g_deg[NN];
__device__ int     g_rowptr[NN + 1];
__device__ int     g_cursor[NN];
__device__ int     g_srcs[EE];
__device__ int     g_blocksum[128];
__device__ int     g_blockoff[128];

// packed fp32x2 FMA (sm_103a FFMA2) — 2 fp32 FMAs per instruction, full precision
__device__ __forceinline__ float2 ffma2(float2 a, float2 b, float2 c)
{
    float2 d;
    asm("fma.rn.f32x2 %0, %1, %2, %3;"
        : "=l"(*reinterpret_cast<unsigned long long*>(&d))
        : "l"(*reinterpret_cast<unsigned long long*>(&a)),
          "l"(*reinterpret_cast<unsigned long long*>(&b)),
          "l"(*reinterpret_cast<unsigned long long*>(&c)));
    return d;
}

// ---------------- init: blocks 0..20 fuse weights, blocks 21.. zero g_deg ----------------
__global__ void k_init(const float* __restrict__ Wr, const float* __restrict__ br,
                       const float* __restrict__ Wu, const float* __restrict__ bu,
                       const float* __restrict__ Wp, const float* __restrict__ bp,
                       const float* __restrict__ W1)
{
    if (blockIdx.x < ZC) {
        int row = blockIdx.x;
        int f   = threadIdx.x;     // 0..127
        const float* v;
        if (row < 5)        v = Wr + row * F;
        else if (row < 12)  v = Wu + (row - 5) * F;
        else if (row < 18)  v = Wp + (row - 12) * F;
        else if (row == 18) v = br;
        else if (row == 19) v = bu;
        else                v = bp;
        float acc = 0.f;
        for (int j = 0; j < F; j++) acc += v[j] * W1[j * F + f];
        g_Ws[row * F + f] = acc;
    } else {
        int i = (blockIdx.x - ZC) * blockDim.x + threadIdx.x;
        if (i < NN) g_deg[i] = 0;
    }
}

// ---------------- histogram ----------------
__global__ void k_hist(const int* __restrict__ dst)
{
    int e = blockIdx.x * blockDim.x + threadIdx.x;
    if (e < EE) atomicAdd(&g_deg[dst[e]], 1);
}

// ---------------- parallel scan (3 stages) ----------------
__global__ void k_scan1()
{
    __shared__ int wsum[8];
    int t = threadIdx.x;               // 0..255
    int lane = t & 31, wid = t >> 5;
    int i0 = blockIdx.x * 1024 + t * 4;
    int v[4], tsum = 0;
    #pragma unroll
    for (int k = 0; k < 4; k++) {
        v[k] = (i0 + k < NN) ? g_deg[i0 + k] : 0;
        tsum += v[k];
    }
    int incl = tsum;
    #pragma unroll
    for (int off = 1; off < 32; off <<= 1) {
        int x = __shfl_up_sync(0xffffffffu, incl, off);
        if (lane >= off) incl += x;
    }
    if (lane == 31) wsum[wid] = incl;
    __syncthreads();
    if (t < 8) {
        int w = wsum[t], wi = w;
        #pragma unroll
        for (int off = 1; off < 8; off <<= 1) {
            int x = __shfl_up_sync(0xffu, wi, off);
            if (t >= off) wi += x;
        }
        wsum[t] = wi - w;
        if (t == 7) g_blocksum[blockIdx.x] = wi;
    }
    __syncthreads();
    int excl = wsum[wid] + (incl - tsum);
    int run = 0;
    #pragma unroll
    for (int k = 0; k < 4; k++) {
        if (i0 + k < NN) g_rowptr[i0 + k] = excl + run;
        run += v[k];
    }
}

__global__ void k_scan2(int nblocks)
{
    __shared__ int ws[4];
    int t = threadIdx.x;               // 0..127
    int lane = t & 31, wid = t >> 5;
    int v = (t < nblocks) ? g_blocksum[t] : 0;
    int incl = v;
    #pragma unroll
    for (int off = 1; off < 32; off <<= 1) {
        int x = __shfl_up_sync(0xffffffffu, incl, off);
        if (lane >= off) incl += x;
    }
    if (lane == 31) ws[wid] = incl;
    __syncthreads();
    if (t == 0) {
        int a = 0;
        #pragma unroll
        for (int i = 0; i < 4; i++) { int x = ws[i]; ws[i] = a; a += x; }
    }
    __syncthreads();
    if (t < nblocks) g_blockoff[t] = ws[wid] + incl - v;
}

__global__ void k_scan3()
{
    int i = blockIdx.x * blockDim.x + threadIdx.x;
    if (i < NN) {
        int r = g_rowptr[i] + g_blockoff[i >> 10];
        g_rowptr[i] = r;
        g_cursor[i] = r;
    }
    if (i == 0) g_rowptr[NN] = EE;
}

// ---------------- scatter ----------------
__global__ void k_scatter(const int* __restrict__ src, const int* __restrict__ dst)
{
    int e = blockIdx.x * blockDim.x + threadIdx.x;
    if (e < EE) {
        int d = dst[e];
        int p = atomicAdd(&g_cursor[d], 1);
        g_srcs[p] = src[e];
    }
}

// ---------------- layer-1 raw aggregate (8 lanes per node, high occupancy) ----------------
__global__ void k_aggz(const float* __restrict__ xr, const float* __restrict__ xu,
                       const float* __restrict__ xp)
{
    int gid  = blockIdx.x * blockDim.x + threadIdx.x;
    int node = gid >> 3;
    if (node >= NN) return;
    int lane = gid & 7;
    int b = g_rowptr[node], e = g_rowptr[node + 1];
    float aR = 0.f, aU = 0.f, aP = 0.f;
    int   cR = 0,   cU = 0,   cP = 0;
    int j = b;
    for (; j + 1 < e; j += 2) {
        int s0 = g_srcs[j];
        int s1 = g_srcs[j + 1];
        if (s0 < N_R)            { if (lane < 5) aR += xr[s0 * 5 + lane]; cR++; }
        else if (s0 < N_R + N_U) { if (lane < 7) aU += xu[(s0 - N_R) * 7 + lane]; cU++; }
        else                     { if (lane < 6) aP += xp[(s0 - N_R - N_U) * 6 + lane]; cP++; }
        if (s1 < N_R)            { if (lane < 5) aR += xr[s1 * 5 + lane]; cR++; }
        else if (s1 < N_R + N_U) { if (lane < 7) aU += xu[(s1 - N_R) * 7 + lane]; cU++; }
        else                     { if (lane < 6) aP += xp[(s1 - N_R - N_U) * 6 + lane]; cP++; }
    }
    if (j < e) {
        int s0 = g_srcs[j];
        if (s0 < N_R)            { if (lane < 5) aR += xr[s0 * 5 + lane]; cR++; }
        else if (s0 < N_R + N_U) { if (lane < 7) aU += xu[(s0 - N_R) * 7 + lane]; cU++; }
        else                     { if (lane < 6) aP += xp[(s0 - N_R - N_U) * 6 + lane]; cP++; }
    }
    float* zr = g_z + (size_t)node * ZC;
    if (lane < 5) zr[lane]      = aR;
    if (lane < 7) zr[5 + lane]  = aU;
    if (lane < 6) zr[12 + lane] = aP;
    if (lane == 7) {
        zr[18] = (float)cR;
        zr[19] = (float)cU;
        zr[20] = (float)cP;
    }
}

// ---------------- 2-layer MLP with FFMA2: h2 = relu(z@Ws)@W2 (half2 out) ----------------
// smem: Wss 2688f | W2p 5200f (float2[20][130] interleaved even/odd cols) | zsm 2688f | hsm 16640f
__global__ void __launch_bounds__(256, 2)
k_mlp(const float* __restrict__ W2)
{
    extern __shared__ float sm[];
    float*  Wss = sm;                              // ZC*F
    float2* W2p = (float2*)(sm + ZC * F);          // C2 * FP2 float2
    float*  zsm = sm + ZC * F + C2 * FP2 * 2;      // TN*ZC
    float*  hsm = zsm + TN * ZC;                   // TN*HP

    int tid = threadIdx.x;            // 0..255
    int nodeBase = blockIdx.x * TN;

    for (int i = tid; i < ZC * F; i += 256) Wss[i] = g_Ws[i];
    // W2p[col2][c] = {W2[c][2*col2], W2[c][2*col2+1]}
    for (int i = tid; i < C2 * F; i += 256) {
        int col2 = i >> 7, c = i & (F - 1);
        W2p[col2 * FP2 + c] = make_float2(W2[c * C + 2 * col2], W2[c * C + 2 * col2 + 1]);
    }
    const float* zg = g_z + (size_t)nodeBase * ZC;   // g_z padded, safe over-read
    for (int i = tid; i < TN * ZC; i += 256) zsm[i] = zg[i];
    __syncthreads();

    // ---- phase A: h = relu(z @ Ws); thread = 8 nodes x 8 cols (4 float2 pairs)
    {
        int ng = tid >> 4;            // 0..15 -> nodes ng*8..+7
        int cl = tid & 15;            // cols [8*cl, 8*cl+8)
        int n0 = ng * 8;
        float2 acc[8][4];
        #pragma unroll
        for (int j = 0; j < 8; j++)
            #pragma unroll
            for (int p = 0; p < 4; p++) acc[j][p] = make_float2(0.f, 0.f);
        #pragma unroll
        for (int k = 0; k < ZC; k++) {
            float4 wA = *(const float4*)&Wss[k * F + 8 * cl];
            float4 wB = *(const float4*)&Wss[k * F + 8 * cl + 4];
            float2 w[4] = { make_float2(wA.x, wA.y), make_float2(wA.z, wA.w),
                            make_float2(wB.x, wB.y), make_float2(wB.z, wB.w) };
            #pragma unroll
            for (int j = 0; j < 8; j++) {
                float z = zsm[(n0 + j) * ZC + k];
                float2 zz = make_float2(z, z);
                #pragma unroll
                for (int p = 0; p < 4; p++) acc[j][p] = ffma2(zz, w[p], acc[j][p]);
            }
        }
        #pragma unroll
        for (int j = 0; j < 8; j++)
            #pragma unroll
            for (int p = 0; p < 4; p++) {
                float2 r = make_float2(fmaxf(acc[j][p].x, 0.f), fmaxf(acc[j][p].y, 0.f));
                *(float2*)&hsm[(n0 + j) * HP + 8 * cl + 2 * p] = r;
            }
    }
    __syncthreads();

    // ---- phase B: h2 = h @ W2; thread = 2 nodes x 5 half2-cols
    {
        int ng = tid >> 2;            // 0..63 -> nodes ng*2, ng*2+1
        int cl = tid & 3;             // col2 [5*cl, 5*cl+5)
        int n0 = ng * 2;
        float2 a[2][5];
        #pragma unroll
        for (int j = 0; j < 2; j++)
            #pragma unroll
            for (int i = 0; i < 5; i++) a[j][i] = make_float2(0.f, 0.f);
        #pragma unroll 4
        for (int c = 0; c < F; c += 2) {
            float2 h0 = *(const float2*)&hsm[(n0 + 0) * HP + c];
            float2 h1 = *(const float2*)&hsm[(n0 + 1) * HP + c];
            float2 h0a = make_float2(h0.x, h0.x), h0b = make_float2(h0.y, h0.y);
            float2 h1a = make_float2(h1.x, h1.x), h1b = make_float2(h1.y, h1.y);
            #pragma unroll
            for (int i = 0; i < 5; i++) {
                float4 ww = *(const float4*)&W2p[(5 * cl + i) * FP2 + c];
                float2 w0 = make_float2(ww.x, ww.y);
                float2 w1 = make_float2(ww.z, ww.w);
                a[0][i] = ffma2(h0a, w0, a[0][i]);
                a[0][i] = ffma2(h0b, w1, a[0][i]);
                a[1][i] = ffma2(h1a, w0, a[1][i]);
                a[1][i] = ffma2(h1b, w1, a[1][i]);
            }
        }
        #pragma unroll
        for (int j = 0; j < 2; j++) {
            int node = nodeBase + n0 + j;
            if (node < NN) {
                #pragma unroll
                for (int i = 0; i < 5; i++)
                    g_h2h[(size_t)node * C2 + 5 * cl + i] = __float22half2_rn(a[j][i]);
            }
        }
    }
}

// ---------------- layer-2 aggregate: warp per node, half2 gather, fp32 accumulate ----------------
__global__ void k_agg2(float* __restrict__ out)
{
    int gw = (blockIdx.x * blockDim.x + threadIdx.x) >> 5;
    if (gw >= NN) return;
    int lane = threadIdx.x & 31;
    if (lane >= C2) return;           // 20 active lanes, one half2 column each
    int b = g_rowptr[gw], e = g_rowptr[gw + 1];
    float2 acc = make_float2(0.f, 0.f);
    int j = b;
    for (; j + 3 < e; j += 4) {
        int s0 = g_srcs[j], s1 = g_srcs[j + 1], s2 = g_srcs[j + 2], s3 = g_srcs[j + 3];
        float2 v0 = __half22float2(g_h2h[(size_t)s0 * C2 + lane]);
        float2 v1 = __half22float2(g_h2h[(size_t)s1 * C2 + lane]);
        float2 v2 = __half22float2(g_h2h[(size_t)s2 * C2 + lane]);
        float2 v3 = __half22float2(g_h2h[(size_t)s3 * C2 + lane]);
        acc.x += (v0.x + v1.x) + (v2.x + v3.x);
        acc.y += (v0.y + v1.y) + (v2.y + v3.y);
    }
    for (; j < e; j++) {
        int s0 = g_srcs[j];
        float2 v0 = __half22float2(g_h2h[(size_t)s0 * C2 + lane]);
        acc.x += v0.x;
        acc.y += v0.y;
    }
    *(float2*)&out[(size_t)gw * C + 2 * lane] = acc;
}

// ---------------- launch ----------------
extern "C" void kernel_launch(void* const* d_in, const int* in_sizes, int n_in,
                              void* d_out, int out_size)
{
    const float* xr = (const float*)d_in[0];
    const float* xu = (const float*)d_in[1];
    const float* xp = (const float*)d_in[2];
    const int*   ei = (const int*)  d_in[3];
    const float* Wr = (const float*)d_in[4];
    const float* br = (const float*)d_in[5];
    const float* Wu = (const float*)d_in[6];
    const float* bu = (const float*)d_in[7];
    const float* Wp = (const float*)d_in[8];
    const float* bp = (const float*)d_in[9];
    const float* W1 = (const float*)d_in[10];
    const float* W2 = (const float*)d_in[11];
    float* out = (float*)d_out;

    const int* src = ei;
    const int* dst = ei + EE;

    const int smem_mlp = (ZC * F + C2 * FP2 * 2 + TN * ZC + TN * HP) * sizeof(float);
    cudaFuncSetAttribute(k_mlp, cudaFuncAttributeMaxDynamicSharedMemorySize, smem_mlp);

    const int nScanBlocks = (NN + 1023) / 1024;   // 98
    const int nZeroBlocks = (NN + 127) / 128;

    k_init<<<ZC + nZeroBlocks, 128>>>(Wr, br, Wu, bu, Wp, bp, W1);
    k_hist<<<(EE + 255) / 256, 256>>>(dst);
    k_scan1<<<nScanBlocks, 256>>>();
    k_scan2<<<1, 128>>>(nScanBlocks);
    k_scan3<<<(NN + 255) / 256, 256>>>();
    k_scatter<<<(EE + 255) / 256, 256>>>(src, dst);
    k_aggz<<<(NN * 8 + 255) / 256, 256>>>(xr, xu, xp);
    k_mlp<<<(NN + TN - 1) / TN, 256, smem_mlp>>>(W2);
    k_agg2<<<(NN * 32 + 255) / 256, 256>>>(out);
}